// round 1
// baseline (speedup 1.0000x reference)
#include <cuda_runtime.h>
#include <cuda_bf16.h>
#include <math.h>

// Problem dims (fixed by reference)
#define B_    16
#define CIN   512
#define COUT  512
#define H_    64
#define W_    64
#define HW    4096      // 64*64
#define SDIM  32
#define OH    128
#define OW    128
#define EPS   1e-8f

// Scratch (device globals; no allocation allowed)
__device__ float g_s[B_ * CIN];        // style modulation s[b, cin]
__device__ float g_demod[B_ * COUT];   // demod[b, cout]
__device__ float g_y[(size_t)B_ * COUT * HW];  // conv output before upsample (134 MB)

// ---------------------------------------------------------------------------
// Kernel A: s[b,cin] = style[b]·mod_w[cin] + mod_b[cin]
//           demod[b,cout] = rsqrt(sum_cin (conv_w[cout,cin]*s[b,cin])^2 + eps)
// One block per batch, 512 threads.
// ---------------------------------------------------------------------------
__global__ __launch_bounds__(512) void mod_kernel(
    const float* __restrict__ style,
    const float* __restrict__ conv_w,
    const float* __restrict__ mod_w,
    const float* __restrict__ mod_b)
{
    int b   = blockIdx.x;
    int tid = threadIdx.x;          // 0..511 == cin
    __shared__ float s_sh[CIN];

    float acc = mod_b[tid];
    const float* st = style + b * SDIM;
    const float* mw = mod_w + tid * SDIM;
#pragma unroll
    for (int k = 0; k < SDIM; k++) acc += st[k] * mw[k];
    s_sh[tid] = acc;
    g_s[b * CIN + tid] = acc;
    __syncthreads();

    int warp = tid >> 5, lane = tid & 31;
    for (int o = warp; o < COUT; o += 16) {
        const float* cw = conv_w + o * CIN;
        float sum = 0.f;
#pragma unroll 4
        for (int i = lane; i < CIN; i += 32) {
            float v = cw[i] * s_sh[i];
            sum += v * v;
        }
#pragma unroll
        for (int off = 16; off; off >>= 1)
            sum += __shfl_xor_sync(0xFFFFFFFFu, sum, off);
        if (lane == 0) g_demod[b * COUT + o] = rsqrtf(sum + EPS);
    }
}

// ---------------------------------------------------------------------------
// Kernel B: batched GEMM  y[b,o,p] = demod[b,o] * sum_i conv_w[o,i]*(s[b,i]*x[b,i,p])
// A = conv_w [COUT, CIN] shared across batches (L2 resident).
// BM=BN=128, BK=8, 256 threads, 8x8 per thread.
// ---------------------------------------------------------------------------
#define BM 128
#define BN 128
#define BK 8

__global__ __launch_bounds__(256) void gemm_kernel(
    const float* __restrict__ x,
    const float* __restrict__ conv_w)
{
    int b     = blockIdx.z;
    int pTile = blockIdx.x * BN;   // pixel tile
    int oTile = blockIdx.y * BM;   // cout tile

    __shared__ float As[BK][BM];
    __shared__ float Bs[BK][BN];

    int tid = threadIdx.x;
    int tx  = tid & 15;            // 0..15 -> n
    int ty  = tid >> 4;            // 0..15 -> m

    float acc[8][8];
#pragma unroll
    for (int m = 0; m < 8; m++)
#pragma unroll
        for (int n = 0; n < 8; n++) acc[m][n] = 0.f;

    const float* xb = x + (size_t)b * CIN * HW;
    const float* sb = g_s + b * CIN;

    int aRow = tid >> 1;           // 0..127
    int aCol = (tid & 1) * 4;      // 0 or 4
    int bRow = tid >> 5;           // 0..7
    int bCol = (tid & 31) * 4;     // 0..124

    for (int k0 = 0; k0 < CIN; k0 += BK) {
        float4 av = *(const float4*)(conv_w + (size_t)(oTile + aRow) * CIN + k0 + aCol);
        As[aCol + 0][aRow] = av.x;
        As[aCol + 1][aRow] = av.y;
        As[aCol + 2][aRow] = av.z;
        As[aCol + 3][aRow] = av.w;

        float4 bv = *(const float4*)(xb + (size_t)(k0 + bRow) * HW + pTile + bCol);
        float sv = sb[k0 + bRow];
        bv.x *= sv; bv.y *= sv; bv.z *= sv; bv.w *= sv;
        *(float4*)&Bs[bRow][bCol] = bv;

        __syncthreads();

#pragma unroll
        for (int k = 0; k < BK; k++) {
            float ra[8], rb[8];
            *(float4*)(ra)     = *(const float4*)&As[k][ty * 8];
            *(float4*)(ra + 4) = *(const float4*)&As[k][ty * 8 + 4];
            *(float4*)(rb)     = *(const float4*)&Bs[k][tx * 8];
            *(float4*)(rb + 4) = *(const float4*)&Bs[k][tx * 8 + 4];
#pragma unroll
            for (int m = 0; m < 8; m++)
#pragma unroll
                for (int n = 0; n < 8; n++)
                    acc[m][n] += ra[m] * rb[n];
        }
        __syncthreads();
    }

    const float* db = g_demod + b * COUT;
    float* yb = g_y + (size_t)b * COUT * HW;
#pragma unroll
    for (int m = 0; m < 8; m++) {
        int o = oTile + ty * 8 + m;
        float d = db[o];
        float4 v0 = make_float4(acc[m][0] * d, acc[m][1] * d, acc[m][2] * d, acc[m][3] * d);
        float4 v1 = make_float4(acc[m][4] * d, acc[m][5] * d, acc[m][6] * d, acc[m][7] * d);
        float* dst = yb + (size_t)o * HW + pTile + tx * 8;
        *(float4*)(dst)     = v0;
        *(float4*)(dst + 4) = v1;
    }
}

// ---------------------------------------------------------------------------
// Kernel C: bilinear x2 upsample, align_corners=False (half-pixel centers).
// Output coord -> input coord: f = (o + 0.5)*0.5 - 0.5 = o*0.5 - 0.25.
// Index clamping reproduces jax.image.resize edge renormalization exactly.
// Each thread writes one float4 (4 consecutive ox).
// ---------------------------------------------------------------------------
__global__ __launch_bounds__(256) void upsample_kernel(float* __restrict__ out)
{
    // total float4s = B_*COUT*OH*(OW/4) = 33,554,432
    unsigned t = blockIdx.x * 256u + threadIdx.x;
    unsigned x4 = t & 31u;          // OW/4 = 32
    unsigned r  = t >> 5;
    unsigned oy = r & 127u;         // OH = 128
    r >>= 7;
    unsigned c  = r & 511u;         // COUT = 512
    unsigned b  = r >> 9;           // B_ = 16

    const float* in = g_y + ((size_t)b * COUT + c) * HW;

    float fy  = oy * 0.5f - 0.25f;
    float y0f = floorf(fy);
    float wy  = fy - y0f;
    int iy0 = max(0, (int)y0f);
    int iy1 = min(H_ - 1, (int)y0f + 1);
    const float* row0 = in + iy0 * W_;
    const float* row1 = in + iy1 * W_;

    float res[4];
#pragma unroll
    for (int j = 0; j < 4; j++) {
        int ox   = x4 * 4 + j;
        float fx  = ox * 0.5f - 0.25f;
        float x0f = floorf(fx);
        float wx  = fx - x0f;
        int ix0 = max(0, (int)x0f);
        int ix1 = min(W_ - 1, (int)x0f + 1);
        float top = row0[ix0] * (1.f - wx) + row0[ix1] * wx;
        float bot = row1[ix0] * (1.f - wx) + row1[ix1] * wx;
        res[j] = top * (1.f - wy) + bot * wy;
    }

    float* dst = out + (((size_t)b * COUT + c) * OH + oy) * OW + x4 * 4;
    *(float4*)dst = make_float4(res[0], res[1], res[2], res[3]);
}

// ---------------------------------------------------------------------------
extern "C" void kernel_launch(void* const* d_in, const int* in_sizes, int n_in,
                              void* d_out, int out_size)
{
    const float* x      = (const float*)d_in[0];  // [16,512,64,64]
    const float* style  = (const float*)d_in[1];  // [16,32]
    const float* conv_w = (const float*)d_in[2];  // [512,512,1,1]
    const float* mod_w  = (const float*)d_in[3];  // [512,32]
    const float* mod_b  = (const float*)d_in[4];  // [512]
    float* out = (float*)d_out;                   // [16,512,128,128]

    mod_kernel<<<B_, 512>>>(style, conv_w, mod_w, mod_b);

    dim3 grid(HW / BN, COUT / BM, B_);            // (32, 4, 16)
    gemm_kernel<<<grid, 256>>>(x, conv_w);

    unsigned total4 = (unsigned)B_ * COUT * OH * (OW / 4);  // 33,554,432
    upsample_kernel<<<total4 / 256, 256>>>(out);
}

// round 3
// speedup vs baseline: 1.9023x; 1.9023x over previous
#include <cuda_runtime.h>
#include <cuda_bf16.h>
#include <cstdint>
#include <math.h>

// Problem dims
#define B_    16
#define CIN   512
#define COUT  512
#define H_    64
#define W_    64
#define HW    4096
#define SDIM  32
#define OH    128
#define OW    128
#define EPS   1e-8f

// Scratch
__device__ float g_s[B_ * CIN];
__device__ float g_demod[B_ * COUT];
__device__ float g_y[(size_t)B_ * COUT * HW];

// ---------------------------------------------------------------------------
// Kernel A: style modulation + demod (parallel: 32 cout-groups x 16 batches)
// ---------------------------------------------------------------------------
__global__ __launch_bounds__(256) void mod_kernel(
    const float* __restrict__ style,
    const float* __restrict__ conv_w,
    const float* __restrict__ mod_w,
    const float* __restrict__ mod_b)
{
    int og = blockIdx.x;
    int b  = blockIdx.y;
    int tid = threadIdx.x;
    __shared__ float s_sh[CIN];

    const float* st = style + b * SDIM;
    for (int i = tid; i < CIN; i += 256) {
        float acc = mod_b[i];
        const float* mw = mod_w + i * SDIM;
#pragma unroll
        for (int k = 0; k < SDIM; k++) acc += st[k] * mw[k];
        s_sh[i] = acc;
        if (og == 0) g_s[b * CIN + i] = acc;
    }
    __syncthreads();

    int wid = tid >> 5, lane = tid & 31;
#pragma unroll
    for (int cc = 0; cc < 2; cc++) {
        int o = og * 16 + wid * 2 + cc;
        const float* cw = conv_w + (size_t)o * CIN;
        float sum = 0.f;
#pragma unroll 4
        for (int i = lane; i < CIN; i += 32) {
            float v = cw[i] * s_sh[i];
            sum += v * v;
        }
#pragma unroll
        for (int off = 16; off; off >>= 1)
            sum += __shfl_xor_sync(0xFFFFFFFFu, sum, off);
        if (lane == 0) g_demod[b * COUT + o] = rsqrtf(sum + EPS);
    }
}

// ---------------------------------------------------------------------------
// Kernel B: batched GEMM with mma.sync.m16n8k8.tf32 (works on base sm_103).
// y[b,o,p] = demod[b,o] * sum_i (conv_w[o,i]*s[b,i]) * x[b,i,p]
// CTA: 128 (o) x 128 (p) x K-chunks of 32. 8 warps, warp tile 64x32.
// A (conv_w, s-scaled, tf32-rounded) via LDG->STS transpose; B (x) via cp.async.
// ---------------------------------------------------------------------------
#define BK 32
#define AST 136      // smem row stride (floats) -> conflict-free fragment LDS
#define BST 136
#define SM_A_FLOATS (2 * BK * AST)      // 8704
#define SM_B_FLOATS (2 * BK * BST)      // 8704
#define SM_GEMM_BYTES ((SM_A_FLOATS + SM_B_FLOATS + CIN) * 4)   // 71680

__device__ __forceinline__ uint32_t smem_u32(const void* p) {
    uint32_t a;
    asm("{ .reg .u64 t; cvta.to.shared.u64 t, %1; cvt.u32.u64 %0, t; }" : "=r"(a) : "l"(p));
    return a;
}

__global__ __launch_bounds__(256, 1) void gemm_mma(
    const float* __restrict__ x,
    const float* __restrict__ conv_w)
{
    extern __shared__ float sm[];
    float* As   = sm;                               // [2][32][AST]
    float* Bs   = sm + SM_A_FLOATS;                 // [2][32][BST]
    float* s_sh = sm + SM_A_FLOATS + SM_B_FLOATS;   // [512]

    int tid = threadIdx.x;
    int wid = tid >> 5, lane = tid & 31;
    int gid = lane >> 2, tg = lane & 3;
    int b = blockIdx.z, oTile = blockIdx.y * 128, pTile = blockIdx.x * 128;
    int wm = (wid >> 2) * 64, wn = (wid & 3) * 32;

    const float* xb = x + (size_t)b * CIN * HW;
    uint32_t bs_u32 = smem_u32(Bs);

    for (int i = tid; i < CIN; i += 256) s_sh[i] = g_s[b * CIN + i];
    __syncthreads();

    // A load: thread -> row m = tid>>1, k-range (tid&1)*16 .. +15 (4 float4)
    int am = tid >> 1, akc = (tid & 1) * 16;
    const float* a_src_base = conv_w + (size_t)(oTile + am) * CIN + akc;
    // B load: thread -> k-row tid>>3, pixel col (tid&7)*16 (4 x 16B cp.async)
    int bkr = tid >> 3, bpc = (tid & 7) * 16;
    const float* b_src_base = xb + (size_t)bkr * HW + pTile + bpc;

    float c[4][4][4];
#pragma unroll
    for (int mt = 0; mt < 4; mt++)
#pragma unroll
        for (int nt = 0; nt < 4; nt++)
#pragma unroll
            for (int q = 0; q < 4; q++) c[mt][nt][q] = 0.f;

    float4 apre[4];

    auto loadA = [&](int k0) {
#pragma unroll
        for (int j = 0; j < 4; j++)
            apre[j] = __ldg((const float4*)(a_src_base + k0) + j);
    };
    auto storeA = [&](int k0, int buf) {
        float* dst = As + buf * BK * AST;
#pragma unroll
        for (int j = 0; j < 4; j++) {
            float v[4] = {apre[j].x, apre[j].y, apre[j].z, apre[j].w};
#pragma unroll
            for (int l = 0; l < 4; l++) {
                int kk = akc + 4 * j + l;
                float t = v[l] * s_sh[k0 + kk];
                uint32_t u;
                asm("cvt.rna.tf32.f32 %0, %1;" : "=r"(u) : "f"(t));
                dst[kk * AST + am] = __uint_as_float(u);
            }
        }
    };
    auto loadB = [&](int k0, int buf) {
        const float* src = b_src_base + (size_t)k0 * HW;
        uint32_t dst = bs_u32 + (buf * BK * BST + bkr * BST + bpc) * 4;
#pragma unroll
        for (int j = 0; j < 4; j++) {
            asm volatile("cp.async.cg.shared.global [%0], [%1], 16;"
                         :: "r"(dst + j * 16), "l"(src + j * 4) : "memory");
        }
    };

    // Prologue: chunk 0
    loadA(0);
    loadB(0, 0);
    asm volatile("cp.async.commit_group;" ::: "memory");
    storeA(0, 0);
    asm volatile("cp.async.wait_group 0;" ::: "memory");
    __syncthreads();

    for (int ch = 0; ch < CIN / BK; ch++) {
        int buf = ch & 1;
        int nxt = ch + 1;
        if (nxt < CIN / BK) {
            loadA(nxt * BK);
            loadB(nxt * BK, nxt & 1);
            asm volatile("cp.async.commit_group;" ::: "memory");
        }

        const float* Ab = As + buf * BK * AST;
        const float* Bb = Bs + buf * BK * BST;
#pragma unroll
        for (int ks = 0; ks < BK; ks += 8) {
            uint32_t af[4][4], bf[4][2];
#pragma unroll
            for (int mt = 0; mt < 4; mt++) {
                int mb = wm + mt * 16;
                af[mt][0] = __float_as_uint(Ab[(ks + tg) * AST + mb + gid]);
                af[mt][1] = __float_as_uint(Ab[(ks + tg) * AST + mb + gid + 8]);
                af[mt][2] = __float_as_uint(Ab[(ks + tg + 4) * AST + mb + gid]);
                af[mt][3] = __float_as_uint(Ab[(ks + tg + 4) * AST + mb + gid + 8]);
            }
#pragma unroll
            for (int nt = 0; nt < 4; nt++) {
                int nb = wn + nt * 8;
                bf[nt][0] = __float_as_uint(Bb[(ks + tg) * BST + nb + gid]);
                bf[nt][1] = __float_as_uint(Bb[(ks + tg + 4) * BST + nb + gid]);
            }
#pragma unroll
            for (int mt = 0; mt < 4; mt++)
#pragma unroll
                for (int nt = 0; nt < 4; nt++) {
                    asm volatile(
                        "mma.sync.aligned.m16n8k8.row.col.f32.tf32.tf32.f32 "
                        "{%0,%1,%2,%3}, {%4,%5,%6,%7}, {%8,%9}, {%0,%1,%2,%3};"
                        : "+f"(c[mt][nt][0]), "+f"(c[mt][nt][1]),
                          "+f"(c[mt][nt][2]), "+f"(c[mt][nt][3])
                        : "r"(af[mt][0]), "r"(af[mt][1]), "r"(af[mt][2]), "r"(af[mt][3]),
                          "r"(bf[nt][0]), "r"(bf[nt][1]));
                }
        }

        if (nxt < CIN / BK) {
            storeA(nxt * BK, nxt & 1);
            asm volatile("cp.async.wait_group 0;" ::: "memory");
        }
        __syncthreads();
    }

    // Epilogue: demod scale, direct STG.64 (32B sectors fully covered)
    const float* db = g_demod + b * COUT;
    float* yb = g_y + (size_t)b * COUT * HW;
#pragma unroll
    for (int mt = 0; mt < 4; mt++) {
        int r0 = oTile + wm + mt * 16 + gid;
        int r1 = r0 + 8;
        float d0 = __ldg(db + r0), d1 = __ldg(db + r1);
#pragma unroll
        for (int nt = 0; nt < 4; nt++) {
            int col = pTile + wn + nt * 8 + tg * 2;
            float2 v0 = make_float2(c[mt][nt][0] * d0, c[mt][nt][1] * d0);
            float2 v1 = make_float2(c[mt][nt][2] * d1, c[mt][nt][3] * d1);
            *(float2*)(yb + (size_t)r0 * HW + col) = v0;
            *(float2*)(yb + (size_t)r1 * HW + col) = v1;
        }
    }
}

// ---------------------------------------------------------------------------
// Kernel C: bilinear x2 upsample, align_corners=False.
// ---------------------------------------------------------------------------
__global__ __launch_bounds__(256) void upsample_kernel(float* __restrict__ out)
{
    unsigned t = blockIdx.x * 256u + threadIdx.x;
    unsigned x4 = t & 31u;
    unsigned r  = t >> 5;
    unsigned oy = r & 127u;
    r >>= 7;
    unsigned c  = r & 511u;
    unsigned b  = r >> 9;

    const float* in = g_y + ((size_t)b * COUT + c) * HW;

    float fy  = oy * 0.5f - 0.25f;
    float y0f = floorf(fy);
    float wy  = fy - y0f;
    int iy0 = max(0, (int)y0f);
    int iy1 = min(H_ - 1, (int)y0f + 1);
    const float* row0 = in + iy0 * W_;
    const float* row1 = in + iy1 * W_;

    float res[4];
#pragma unroll
    for (int j = 0; j < 4; j++) {
        int ox   = x4 * 4 + j;
        float fx  = ox * 0.5f - 0.25f;
        float x0f = floorf(fx);
        float wx  = fx - x0f;
        int ix0 = max(0, (int)x0f);
        int ix1 = min(W_ - 1, (int)x0f + 1);
        float top = row0[ix0] * (1.f - wx) + row0[ix1] * wx;
        float bot = row1[ix0] * (1.f - wx) + row1[ix1] * wx;
        res[j] = top * (1.f - wy) + bot * wy;
    }

    float* dst = out + (((size_t)b * COUT + c) * OH + oy) * OW + x4 * 4;
    *(float4*)dst = make_float4(res[0], res[1], res[2], res[3]);
}

// ---------------------------------------------------------------------------
extern "C" void kernel_launch(void* const* d_in, const int* in_sizes, int n_in,
                              void* d_out, int out_size)
{
    const float* x      = (const float*)d_in[0];
    const float* style  = (const float*)d_in[1];
    const float* conv_w = (const float*)d_in[2];
    const float* mod_w  = (const float*)d_in[3];
    const float* mod_b  = (const float*)d_in[4];
    float* out = (float*)d_out;

    static int attr_set = 0;
    if (!attr_set) {
        cudaFuncSetAttribute(gemm_mma, cudaFuncAttributeMaxDynamicSharedMemorySize, SM_GEMM_BYTES);
        attr_set = 1;
    }

    dim3 mgrid(32, 16);
    mod_kernel<<<mgrid, 256>>>(style, conv_w, mod_w, mod_b);

    dim3 ggrid(HW / 128, COUT / 128, B_);   // (32, 4, 16) = 2048 CTAs
    gemm_mma<<<ggrid, 256, SM_GEMM_BYTES>>>(x, conv_w);

    unsigned total4 = (unsigned)B_ * COUT * OH * (OW / 4);
    upsample_kernel<<<total4 / 256, 256>>>(out);
}

// round 4
// speedup vs baseline: 1.9950x; 1.0488x over previous
#include <cuda_runtime.h>
#include <cuda_bf16.h>
#include <cstdint>
#include <math.h>

// Problem dims
#define B_    16
#define CIN   512
#define COUT  512
#define H_    64
#define W_    64
#define HW    4096
#define SDIM  32
#define OH    128
#define OW    128
#define EPS   1e-8f

// Scratch
__device__ float g_wmod[(size_t)B_ * COUT * CIN];   // 16 MB: demod-folded, tf32-rounded weights
__device__ float g_y[(size_t)B_ * COUT * HW];       // 134 MB conv output

// ---------------------------------------------------------------------------
// Kernel A: fused modulation + demod + weight materialization.
// w[b,o,k] = cvt_rna_tf32( conv_w[o,k] * s[b,k] * rsqrt(sum_k (conv_w*s)^2 + eps) )
// grid (32 o-groups of 16, 16 batches), 256 threads (8 warps x 2 couts each).
// ---------------------------------------------------------------------------
__global__ __launch_bounds__(256) void wmod_kernel(
    const float* __restrict__ style,
    const float* __restrict__ conv_w,
    const float* __restrict__ mod_w,
    const float* __restrict__ mod_b)
{
    int og = blockIdx.x;     // couts og*16 .. og*16+15
    int b  = blockIdx.y;
    int tid = threadIdx.x;
    __shared__ float s_sh[CIN];
    __shared__ float prod[16][CIN];   // 32 KB staging

    const float* st = style + b * SDIM;
    for (int i = tid; i < CIN; i += 256) {
        float acc = mod_b[i];
        const float* mw = mod_w + i * SDIM;
#pragma unroll
        for (int k = 0; k < SDIM; k++) acc += st[k] * mw[k];
        s_sh[i] = acc;
    }
    __syncthreads();

    int wid = tid >> 5, lane = tid & 31;
#pragma unroll
    for (int cc = 0; cc < 2; cc++) {
        int ol = wid * 2 + cc;             // 0..15
        int o  = og * 16 + ol;
        const float* cw = conv_w + (size_t)o * CIN;
        float sum = 0.f;
#pragma unroll 4
        for (int i = lane; i < CIN; i += 32) {
            float t = cw[i] * s_sh[i];
            prod[ol][i] = t;
            sum += t * t;
        }
#pragma unroll
        for (int off = 16; off; off >>= 1)
            sum += __shfl_xor_sync(0xFFFFFFFFu, sum, off);
        float dm = rsqrtf(sum + EPS);      // uniform across warp after reduction
        float* dst = g_wmod + ((size_t)b * COUT + o) * CIN;
#pragma unroll 4
        for (int i = lane; i < CIN; i += 32) {
            float t = prod[ol][i] * dm;
            uint32_t u;
            asm("cvt.rna.tf32.f32 %0, %1;" : "=r"(u) : "f"(t));
            dst[i] = __uint_as_float(u);
        }
    }
}

// ---------------------------------------------------------------------------
// Kernel B: batched GEMM, mma.sync.m16n8k8.tf32, all operands via cp.async.
// y[b,o,p] = sum_k g_wmod[b,o,k] * x[b,k,p]
// CTA 128(o) x 128(p), K chunks of 32, double-buffered. 8 warps, warp 64x32.
// 2 CTAs/SM (regs <=128, smem 69 KB).
// ---------------------------------------------------------------------------
#define BK 32
#define ASTR 36      // A smem row stride (floats): 144B, 16B-aligned, conflict-free
#define BSTR 132     // B smem row stride (floats): 528B, 16B-aligned, conflict-free
#define SM_A_FL (BK * ASTR)          // per stage: 32 rows? no: A is [128 m][36]
#define SM_ASTAGE (128 * ASTR)       // 4608 floats
#define SM_BSTAGE (BK * BSTR)        // 4224 floats
#define SM_GEMM_BYTES (2 * (SM_ASTAGE + SM_BSTAGE) * 4)   // 70656

__device__ __forceinline__ uint32_t smem_u32(const void* p) {
    uint32_t a;
    asm("{ .reg .u64 t; cvta.to.shared.u64 t, %1; cvt.u32.u64 %0, t; }" : "=r"(a) : "l"(p));
    return a;
}

__global__ __launch_bounds__(256, 2) void gemm_mma(
    const float* __restrict__ x)
{
    extern __shared__ float sm[];
    float* As = sm;                              // [2][128][ASTR]
    float* Bs = sm + 2 * SM_ASTAGE;              // [2][BK][BSTR]

    int tid = threadIdx.x;
    int wid = tid >> 5, lane = tid & 31;
    int gid = lane >> 2, tg = lane & 3;
    int b = blockIdx.z, oTile = blockIdx.y * 128, pTile = blockIdx.x * 128;
    int wm = (wid >> 2) * 64, wn = (wid & 3) * 32;

    const float* wsrc = g_wmod + ((size_t)b * COUT + oTile) * CIN;
    const float* xb   = x + (size_t)b * CIN * HW;

    uint32_t as_u = smem_u32(As);
    uint32_t bs_u = smem_u32(Bs);

    // A: thread -> row m = tid>>1, k offset (tid&1)*16, 4x 16B chunks
    int am = tid >> 1, akc = (tid & 1) * 16;
    const float* a_src = wsrc + (size_t)am * CIN + akc;
    uint32_t a_dst = as_u + (am * ASTR + akc) * 4;
    // B: thread -> k row tid>>3, pixel (tid&7)*16, 4x 16B chunks
    int bkr = tid >> 3, bpc = (tid & 7) * 16;
    const float* b_src = xb + (size_t)bkr * HW + pTile + bpc;
    uint32_t b_dst = bs_u + (bkr * BSTR + bpc) * 4;

    auto issue = [&](int ch) {
        int buf = ch & 1;
        const float* as_ = a_src + ch * BK;
        uint32_t ad = a_dst + buf * SM_ASTAGE * 4;
#pragma unroll
        for (int j = 0; j < 4; j++)
            asm volatile("cp.async.cg.shared.global [%0], [%1], 16;"
                         :: "r"(ad + j * 16), "l"(as_ + j * 4) : "memory");
        const float* bs_ = b_src + (size_t)(ch * BK) * HW;
        uint32_t bd = b_dst + buf * SM_BSTAGE * 4;
#pragma unroll
        for (int j = 0; j < 4; j++)
            asm volatile("cp.async.cg.shared.global [%0], [%1], 16;"
                         :: "r"(bd + j * 16), "l"(bs_ + j * 4) : "memory");
        asm volatile("cp.async.commit_group;" ::: "memory");
    };

    float c[4][4][4];
#pragma unroll
    for (int mt = 0; mt < 4; mt++)
#pragma unroll
        for (int nt = 0; nt < 4; nt++)
#pragma unroll
            for (int q = 0; q < 4; q++) c[mt][nt][q] = 0.f;

    issue(0);

    const int NCH = CIN / BK;   // 16
    for (int ch = 0; ch < NCH; ch++) {
        if (ch + 1 < NCH) {
            issue(ch + 1);
            asm volatile("cp.async.wait_group 1;" ::: "memory");
        } else {
            asm volatile("cp.async.wait_group 0;" ::: "memory");
        }
        __syncthreads();

        int buf = ch & 1;
        const float* Ab = As + buf * SM_ASTAGE;
        const float* Bb = Bs + buf * SM_BSTAGE;
#pragma unroll
        for (int ks = 0; ks < BK; ks += 8) {
            uint32_t af[4][4], bf[4][2];
#pragma unroll
            for (int mt = 0; mt < 4; mt++) {
                int mb = wm + mt * 16;
                af[mt][0] = __float_as_uint(Ab[(mb + gid) * ASTR + ks + tg]);
                af[mt][1] = __float_as_uint(Ab[(mb + gid + 8) * ASTR + ks + tg]);
                af[mt][2] = __float_as_uint(Ab[(mb + gid) * ASTR + ks + tg + 4]);
                af[mt][3] = __float_as_uint(Ab[(mb + gid + 8) * ASTR + ks + tg + 4]);
            }
#pragma unroll
            for (int nt = 0; nt < 4; nt++) {
                int nb = wn + nt * 8;
                bf[nt][0] = __float_as_uint(Bb[(ks + tg) * BSTR + nb + gid]);
                bf[nt][1] = __float_as_uint(Bb[(ks + tg + 4) * BSTR + nb + gid]);
            }
#pragma unroll
            for (int mt = 0; mt < 4; mt++)
#pragma unroll
                for (int nt = 0; nt < 4; nt++) {
                    asm volatile(
                        "mma.sync.aligned.m16n8k8.row.col.f32.tf32.tf32.f32 "
                        "{%0,%1,%2,%3}, {%4,%5,%6,%7}, {%8,%9}, {%0,%1,%2,%3};"
                        : "+f"(c[mt][nt][0]), "+f"(c[mt][nt][1]),
                          "+f"(c[mt][nt][2]), "+f"(c[mt][nt][3])
                        : "r"(af[mt][0]), "r"(af[mt][1]), "r"(af[mt][2]), "r"(af[mt][3]),
                          "r"(bf[nt][0]), "r"(bf[nt][1]));
                }
        }
        __syncthreads();
    }

    // Epilogue: demod already folded into weights — pure store.
    float* yb = g_y + (size_t)b * COUT * HW;
#pragma unroll
    for (int mt = 0; mt < 4; mt++) {
        int r0 = oTile + wm + mt * 16 + gid;
        int r1 = r0 + 8;
#pragma unroll
        for (int nt = 0; nt < 4; nt++) {
            int col = pTile + wn + nt * 8 + tg * 2;
            *(float2*)(yb + (size_t)r0 * HW + col) = make_float2(c[mt][nt][0], c[mt][nt][1]);
            *(float2*)(yb + (size_t)r1 * HW + col) = make_float2(c[mt][nt][2], c[mt][nt][3]);
        }
    }
}

// ---------------------------------------------------------------------------
// Kernel C: bilinear x2 upsample, align_corners=False.
// ---------------------------------------------------------------------------
__global__ __launch_bounds__(256) void upsample_kernel(float* __restrict__ out)
{
    unsigned t = blockIdx.x * 256u + threadIdx.x;
    unsigned x4 = t & 31u;
    unsigned r  = t >> 5;
    unsigned oy = r & 127u;
    r >>= 7;
    unsigned c  = r & 511u;
    unsigned b  = r >> 9;

    const float* in = g_y + ((size_t)b * COUT + c) * HW;

    float fy  = oy * 0.5f - 0.25f;
    float y0f = floorf(fy);
    float wy  = fy - y0f;
    int iy0 = max(0, (int)y0f);
    int iy1 = min(H_ - 1, (int)y0f + 1);
    const float* row0 = in + iy0 * W_;
    const float* row1 = in + iy1 * W_;

    float res[4];
#pragma unroll
    for (int j = 0; j < 4; j++) {
        int ox   = x4 * 4 + j;
        float fx  = ox * 0.5f - 0.25f;
        float x0f = floorf(fx);
        float wx  = fx - x0f;
        int ix0 = max(0, (int)x0f);
        int ix1 = min(W_ - 1, (int)x0f + 1);
        float top = row0[ix0] * (1.f - wx) + row0[ix1] * wx;
        float bot = row1[ix0] * (1.f - wx) + row1[ix1] * wx;
        res[j] = top * (1.f - wy) + bot * wy;
    }

    float* dst = out + (((size_t)b * COUT + c) * OH + oy) * OW + x4 * 4;
    *(float4*)dst = make_float4(res[0], res[1], res[2], res[3]);
}

// ---------------------------------------------------------------------------
extern "C" void kernel_launch(void* const* d_in, const int* in_sizes, int n_in,
                              void* d_out, int out_size)
{
    const float* x      = (const float*)d_in[0];
    const float* style  = (const float*)d_in[1];
    const float* conv_w = (const float*)d_in[2];
    const float* mod_w  = (const float*)d_in[3];
    const float* mod_b  = (const float*)d_in[4];
    float* out = (float*)d_out;

    cudaFuncSetAttribute(gemm_mma, cudaFuncAttributeMaxDynamicSharedMemorySize, SM_GEMM_BYTES);

    dim3 wgrid(32, 16);
    wmod_kernel<<<wgrid, 256>>>(style, conv_w, mod_w, mod_b);

    dim3 ggrid(HW / 128, COUT / 128, B_);   // (32, 4, 16) = 2048 CTAs
    gemm_mma<<<ggrid, 256, SM_GEMM_BYTES>>>(x);

    unsigned total4 = (unsigned)B_ * COUT * OH * (OW / 4);
    upsample_kernel<<<total4 / 256, 256>>>(out);
}

// round 5
// speedup vs baseline: 2.5078x; 1.2570x over previous
#include <cuda_runtime.h>
#include <cuda_bf16.h>
#include <cstdint>
#include <math.h>

// Problem dims
#define B_    16
#define CIN   512
#define COUT  512
#define H_    64
#define W_    64
#define HW    4096
#define SDIM  32
#define OH    128
#define OW    128
#define EPS   1e-8f

// Scratch
__device__ float g_s[B_ * CIN];
__device__ float g_demod[B_ * COUT];
__device__ float g_wmod[(size_t)B_ * COUT * CIN];   // fragment-ordered tf32 weights (16 MB)
__device__ float g_y[(size_t)B_ * COUT * HW];       // conv output (134 MB)

// ---------------------------------------------------------------------------
// Kernel A1: s[b,cin] and demod[b,cout]. grid (8 og, 16 b), 256 threads.
// Each block: full s (shared), 64 couts demod.
// ---------------------------------------------------------------------------
__global__ __launch_bounds__(256) void mod_demod_kernel(
    const float* __restrict__ style,
    const float* __restrict__ conv_w,
    const float* __restrict__ mod_w,
    const float* __restrict__ mod_b)
{
    int og = blockIdx.x;      // 0..7 -> couts og*64..+63
    int b  = blockIdx.y;
    int tid = threadIdx.x;
    __shared__ float s_sh[CIN];

    const float* st = style + b * SDIM;
#pragma unroll
    for (int rep = 0; rep < 2; rep++) {
        int i = tid + rep * 256;
        float acc = mod_b[i];
        const float* mw = mod_w + i * SDIM;
#pragma unroll
        for (int k = 0; k < SDIM; k++) acc += st[k] * mw[k];
        s_sh[i] = acc;
        if (og == 0) g_s[b * CIN + i] = acc;
    }
    __syncthreads();

    int wid = tid >> 5, lane = tid & 31;
#pragma unroll
    for (int cc = 0; cc < 8; cc++) {
        int o = og * 64 + wid * 8 + cc;
        const float* cw = conv_w + (size_t)o * CIN;
        float sum = 0.f;
#pragma unroll
        for (int it = 0; it < 4; it++) {
            int k4 = lane + it * 32;           // float4 index
            float4 v = __ldg((const float4*)cw + k4);
            int k = k4 * 4;
            float t0 = v.x * s_sh[k], t1 = v.y * s_sh[k + 1];
            float t2 = v.z * s_sh[k + 2], t3 = v.w * s_sh[k + 3];
            sum += t0 * t0 + t1 * t1 + t2 * t2 + t3 * t3;
        }
#pragma unroll
        for (int off = 16; off; off >>= 1)
            sum += __shfl_xor_sync(0xFFFFFFFFu, sum, off);
        if (lane == 0) g_demod[b * COUT + o] = rsqrtf(sum + EPS);
    }
}

// ---------------------------------------------------------------------------
// Kernel A2: write g_wmod in mma-fragment order.
// Layout: chunk-block (b, ot, c) = 4096 contiguous floats:
//   idx = ((g*16 + s*4 + mt)*32 + l)*4 + q
// where value(q) = cvt_rna_tf32( conv_w[o,k] * s[b,k] * demod[b,o] ),
//   o = ot*128 + g*64 + mt*16 + (l>>2) + (q&1)*8
//   k = c*32 + s*8 + (l&3) + (q>>1)*4
// grid (16 c, 4 ot, 16 b), 256 threads; thread = (g, l, s).
// ---------------------------------------------------------------------------
__global__ __launch_bounds__(256) void wfrag_kernel(
    const float* __restrict__ conv_w)
{
    int c  = blockIdx.x;
    int ot = blockIdx.y;
    int b  = blockIdx.z;
    int tid = threadIdx.x;
    int g = tid >> 7, rem = tid & 127;
    int l = rem >> 2, s = rem & 3;
    int gid = l >> 2, tg = l & 3;

    int obase = ot * 128 + g * 64 + gid;
    int kbase = c * 32 + s * 8 + tg;
    float sv0 = __ldg(g_s + b * CIN + kbase);
    float sv1 = __ldg(g_s + b * CIN + kbase + 4);

    float* dst = g_wmod + ((size_t)((b * 4 + ot) * 16 + c)) * 4096
               + ((g * 16 + s * 4) * 32 + l) * 4;

#pragma unroll
    for (int mt = 0; mt < 4; mt++) {
        int o0 = obase + mt * 16;
        int o1 = o0 + 8;
        float d0 = __ldg(g_demod + b * COUT + o0);
        float d1 = __ldg(g_demod + b * COUT + o1);
        float v0 = __ldg(conv_w + (size_t)o0 * CIN + kbase)     * sv0 * d0;
        float v1 = __ldg(conv_w + (size_t)o1 * CIN + kbase)     * sv0 * d1;
        float v2 = __ldg(conv_w + (size_t)o0 * CIN + kbase + 4) * sv1 * d0;
        float v3 = __ldg(conv_w + (size_t)o1 * CIN + kbase + 4) * sv1 * d1;
        uint4 u;
        asm("cvt.rna.tf32.f32 %0, %1;" : "=r"(u.x) : "f"(v0));
        asm("cvt.rna.tf32.f32 %0, %1;" : "=r"(u.y) : "f"(v1));
        asm("cvt.rna.tf32.f32 %0, %1;" : "=r"(u.z) : "f"(v2));
        asm("cvt.rna.tf32.f32 %0, %1;" : "=r"(u.w) : "f"(v3));
        *(uint4*)(dst + mt * 128) = u;
    }
}

// ---------------------------------------------------------------------------
// Kernel B: batched GEMM, mma.sync.m16n8k8.tf32.
// A in fragment order (LDS.128, conflict-free); B natural layout, stride 136
// (conflict-free). 3-stage cp.async pipeline. CTA 128x128, 8 warps 64x32.
// ---------------------------------------------------------------------------
#define BK 32
#define BSTR 136
#define A_STAGE 4096                 // floats
#define B_STAGE (BK * BSTR)          // 4352 floats
#define STAGE_FL (A_STAGE + B_STAGE) // 8448 floats
#define NSTAGE 3
#define SM_GEMM_BYTES (NSTAGE * STAGE_FL * 4)   // 101376

__device__ __forceinline__ uint32_t smem_u32(const void* p) {
    uint32_t a;
    asm("{ .reg .u64 t; cvta.to.shared.u64 t, %1; cvt.u32.u64 %0, t; }" : "=r"(a) : "l"(p));
    return a;
}

__global__ __launch_bounds__(256, 2) void gemm_mma(
    const float* __restrict__ x)
{
    extern __shared__ float sm[];

    int tid = threadIdx.x;
    int wid = tid >> 5, lane = tid & 31;
    int gid = lane >> 2, tg = lane & 3;
    int b = blockIdx.z, oTile = blockIdx.y * 128, pTile = blockIdx.x * 128;
    int g = wid >> 2, wn = (wid & 3) * 32;

    const float* aglob = g_wmod + ((size_t)((b * 4 + blockIdx.y) * 16)) * 4096;
    const float* xb    = x + (size_t)b * CIN * HW;

    uint32_t sm_u = smem_u32(sm);
    // B per-thread cp.async coords
    int bkr = tid >> 3, bpc = (tid & 7) * 16;
    const float* b_src = xb + (size_t)bkr * HW + pTile + bpc;

    auto issue = [&](int ch) {
        int buf = ch % NSTAGE;
        uint32_t stage = sm_u + buf * STAGE_FL * 4;
        // A: 4096 contiguous floats; thread copies 4 x 16B
        const float* as_ = aglob + ch * 4096 + tid * 4;
        uint32_t ad = stage + tid * 16;
#pragma unroll
        for (int j = 0; j < 4; j++)
            asm volatile("cp.async.cg.shared.global [%0], [%1], 16;"
                         :: "r"(ad + j * 4096), "l"(as_ + j * 1024) : "memory");
        // B: [32][136] stride
        const float* bs_ = b_src + (size_t)(ch * BK) * HW;
        uint32_t bd = stage + (A_STAGE + bkr * BSTR + bpc) * 4;
#pragma unroll
        for (int j = 0; j < 4; j++)
            asm volatile("cp.async.cg.shared.global [%0], [%1], 16;"
                         :: "r"(bd + j * 16), "l"(bs_ + j * 4) : "memory");
        asm volatile("cp.async.commit_group;" ::: "memory");
    };

    float c[4][4][4];
#pragma unroll
    for (int mt = 0; mt < 4; mt++)
#pragma unroll
        for (int nt = 0; nt < 4; nt++)
#pragma unroll
            for (int q = 0; q < 4; q++) c[mt][nt][q] = 0.f;

    issue(0);
    issue(1);

    const int NCH = CIN / BK;   // 16
    for (int ch = 0; ch < NCH; ch++) {
        if (ch + 2 < NCH) {
            issue(ch + 2);
            asm volatile("cp.async.wait_group 2;" ::: "memory");
        } else if (ch + 1 < NCH) {
            asm volatile("cp.async.wait_group 1;" ::: "memory");
        } else {
            asm volatile("cp.async.wait_group 0;" ::: "memory");
        }
        __syncthreads();

        int buf = ch % NSTAGE;
        const float* Ab = sm + buf * STAGE_FL + g * 2048;
        const float* Bb = sm + buf * STAGE_FL + A_STAGE;

#pragma unroll
        for (int s = 0; s < 4; s++) {
            int ks = s * 8;
            uint32_t af[4][4], bf[4][2];
#pragma unroll
            for (int mt = 0; mt < 4; mt++) {
                float4 av = *(const float4*)(Ab + ((s * 4 + mt) * 32 + lane) * 4);
                af[mt][0] = __float_as_uint(av.x);
                af[mt][1] = __float_as_uint(av.y);
                af[mt][2] = __float_as_uint(av.z);
                af[mt][3] = __float_as_uint(av.w);
            }
#pragma unroll
            for (int nt = 0; nt < 4; nt++) {
                int nb = wn + nt * 8;
                bf[nt][0] = __float_as_uint(Bb[(ks + tg) * BSTR + nb + gid]);
                bf[nt][1] = __float_as_uint(Bb[(ks + tg + 4) * BSTR + nb + gid]);
            }
#pragma unroll
            for (int mt = 0; mt < 4; mt++)
#pragma unroll
                for (int nt = 0; nt < 4; nt++) {
                    asm volatile(
                        "mma.sync.aligned.m16n8k8.row.col.f32.tf32.tf32.f32 "
                        "{%0,%1,%2,%3}, {%4,%5,%6,%7}, {%8,%9}, {%0,%1,%2,%3};"
                        : "+f"(c[mt][nt][0]), "+f"(c[mt][nt][1]),
                          "+f"(c[mt][nt][2]), "+f"(c[mt][nt][3])
                        : "r"(af[mt][0]), "r"(af[mt][1]), "r"(af[mt][2]), "r"(af[mt][3]),
                          "r"(bf[nt][0]), "r"(bf[nt][1]));
                }
        }
        __syncthreads();
    }

    // Epilogue: demod already folded into A — pure store.
    float* yb = g_y + (size_t)b * COUT * HW;
#pragma unroll
    for (int mt = 0; mt < 4; mt++) {
        int r0 = oTile + g * 64 + mt * 16 + gid;
        int r1 = r0 + 8;
#pragma unroll
        for (int nt = 0; nt < 4; nt++) {
            int col = pTile + wn + nt * 8 + tg * 2;
            *(float2*)(yb + (size_t)r0 * HW + col) = make_float2(c[mt][nt][0], c[mt][nt][1]);
            *(float2*)(yb + (size_t)r1 * HW + col) = make_float2(c[mt][nt][2], c[mt][nt][3]);
        }
    }
}

// ---------------------------------------------------------------------------
// Kernel C: bilinear x2 upsample, align_corners=False.
// ---------------------------------------------------------------------------
__global__ __launch_bounds__(256) void upsample_kernel(float* __restrict__ out)
{
    unsigned t = blockIdx.x * 256u + threadIdx.x;
    unsigned x4 = t & 31u;
    unsigned r  = t >> 5;
    unsigned oy = r & 127u;
    r >>= 7;
    unsigned c  = r & 511u;
    unsigned b  = r >> 9;

    const float* in = g_y + ((size_t)b * COUT + c) * HW;

    float fy  = oy * 0.5f - 0.25f;
    float y0f = floorf(fy);
    float wy  = fy - y0f;
    int iy0 = max(0, (int)y0f);
    int iy1 = min(H_ - 1, (int)y0f + 1);
    const float* row0 = in + iy0 * W_;
    const float* row1 = in + iy1 * W_;

    float res[4];
#pragma unroll
    for (int j = 0; j < 4; j++) {
        int ox   = x4 * 4 + j;
        float fx  = ox * 0.5f - 0.25f;
        float x0f = floorf(fx);
        float wx  = fx - x0f;
        int ix0 = max(0, (int)x0f);
        int ix1 = min(W_ - 1, (int)x0f + 1);
        float top = row0[ix0] * (1.f - wx) + row0[ix1] * wx;
        float bot = row1[ix0] * (1.f - wx) + row1[ix1] * wx;
        res[j] = top * (1.f - wy) + bot * wy;
    }

    float* dst = out + (((size_t)b * COUT + c) * OH + oy) * OW + x4 * 4;
    *(float4*)dst = make_float4(res[0], res[1], res[2], res[3]);
}

// ---------------------------------------------------------------------------
extern "C" void kernel_launch(void* const* d_in, const int* in_sizes, int n_in,
                              void* d_out, int out_size)
{
    const float* x      = (const float*)d_in[0];
    const float* style  = (const float*)d_in[1];
    const float* conv_w = (const float*)d_in[2];
    const float* mod_w  = (const float*)d_in[3];
    const float* mod_b  = (const float*)d_in[4];
    float* out = (float*)d_out;

    cudaFuncSetAttribute(gemm_mma, cudaFuncAttributeMaxDynamicSharedMemorySize, SM_GEMM_BYTES);

    dim3 mgrid(8, 16);
    mod_demod_kernel<<<mgrid, 256>>>(style, conv_w, mod_w, mod_b);

    dim3 fgrid(16, 4, 16);
    wfrag_kernel<<<fgrid, 256>>>(conv_w);

    dim3 ggrid(HW / 128, COUT / 128, B_);   // (32, 4, 16) = 2048 CTAs
    gemm_mma<<<ggrid, 256, SM_GEMM_BYTES>>>(x);

    unsigned total4 = (unsigned)B_ * COUT * OH * (OW / 4);
    upsample_kernel<<<total4 / 256, 256>>>(out);
}

// round 6
// speedup vs baseline: 3.9114x; 1.5597x over previous
#include <cuda_runtime.h>
#include <cuda_fp16.h>
#include <cstdint>
#include <math.h>

// Problem dims
#define B_    16
#define CIN   512
#define COUT  512
#define H_    64
#define W_    64
#define HW    4096
#define SDIM  32
#define OH    128
#define OW    128
#define EPS   1e-8f

// Scratch
__device__ float    g_s[B_ * CIN];
__device__ float    g_demod[B_ * COUT];
__device__ uint32_t g_wh[(size_t)B_ * COUT * CIN / 2];   // fp16 fragment-ordered weights (8 MB)
__device__ uint32_t g_xh[(size_t)B_ * (CIN / 2) * HW];   // half2-paired x (67 MB)
__device__ float    g_y[(size_t)B_ * COUT * HW];         // conv output (134 MB)

// ---------------------------------------------------------------------------
// Kernel A1: s[b,cin], demod[b,cout]. grid (8, 16), 256 threads.
// ---------------------------------------------------------------------------
__global__ __launch_bounds__(256) void mod_demod_kernel(
    const float* __restrict__ style,
    const float* __restrict__ conv_w,
    const float* __restrict__ mod_w,
    const float* __restrict__ mod_b)
{
    int og = blockIdx.x;
    int b  = blockIdx.y;
    int tid = threadIdx.x;
    __shared__ float s_sh[CIN];

    const float* st = style + b * SDIM;
#pragma unroll
    for (int rep = 0; rep < 2; rep++) {
        int i = tid + rep * 256;
        float acc = mod_b[i];
        const float* mw = mod_w + i * SDIM;
#pragma unroll
        for (int k = 0; k < SDIM; k++) acc += st[k] * mw[k];
        s_sh[i] = acc;
        if (og == 0) g_s[b * CIN + i] = acc;
    }
    __syncthreads();

    int wid = tid >> 5, lane = tid & 31;
#pragma unroll
    for (int cc = 0; cc < 8; cc++) {
        int o = og * 64 + wid * 8 + cc;
        const float* cw = conv_w + (size_t)o * CIN;
        float sum = 0.f;
#pragma unroll
        for (int it = 0; it < 4; it++) {
            int k4 = lane + it * 32;
            float4 v = __ldg((const float4*)cw + k4);
            int k = k4 * 4;
            float t0 = v.x * s_sh[k], t1 = v.y * s_sh[k + 1];
            float t2 = v.z * s_sh[k + 2], t3 = v.w * s_sh[k + 3];
            sum += t0 * t0 + t1 * t1 + t2 * t2 + t3 * t3;
        }
#pragma unroll
        for (int off = 16; off; off >>= 1)
            sum += __shfl_xor_sync(0xFFFFFFFFu, sum, off);
        if (lane == 0) g_demod[b * COUT + o] = rsqrtf(sum + EPS);
    }
}

// ---------------------------------------------------------------------------
// Kernel A2: fp16 weights in m16n8k16 fragment order.
// chunk-block (b, ot, c) = 2048 uint32:  idx = fgrp*128 + lane*4 + r
//   fgrp = ((g*2+s)*4+mt),  o = ot*128+g*64+mt*16+gid (+8 for r odd),
//   k = c*32+s*16+tg*2 (+8 for r>=2); each uint32 = half2(k, k+1).
// grid (16 c, 4 ot, 16 b), 256 threads.
// ---------------------------------------------------------------------------
__global__ __launch_bounds__(256) void wfrag_kernel(
    const float* __restrict__ conv_w)
{
    int c  = blockIdx.x;
    int ot = blockIdx.y;
    int b  = blockIdx.z;
    int tid = threadIdx.x;
    int lane = tid & 31, fg = tid >> 5;
    int gid = lane >> 2, tg = lane & 3;

    uint32_t* cb = g_wh + ((size_t)((b * 4 + ot) * 16 + c)) * 2048;

#pragma unroll
    for (int rep = 0; rep < 2; rep++) {
        int fgrp = fg + rep * 8;
        int g  = fgrp >> 3;
        int s  = (fgrp >> 2) & 1;
        int mt = fgrp & 3;
        int o0 = ot * 128 + g * 64 + mt * 16 + gid;
        int o1 = o0 + 8;
        int k0 = c * 32 + s * 16 + tg * 2;

        float d0 = __ldg(g_demod + b * COUT + o0);
        float d1 = __ldg(g_demod + b * COUT + o1);
        float s00 = __ldg(g_s + b * CIN + k0);
        float s01 = __ldg(g_s + b * CIN + k0 + 1);
        float s08 = __ldg(g_s + b * CIN + k0 + 8);
        float s09 = __ldg(g_s + b * CIN + k0 + 9);

        float2 w0a = __ldg((const float2*)(conv_w + (size_t)o0 * CIN + k0));
        float2 w0b = __ldg((const float2*)(conv_w + (size_t)o0 * CIN + k0 + 8));
        float2 w1a = __ldg((const float2*)(conv_w + (size_t)o1 * CIN + k0));
        float2 w1b = __ldg((const float2*)(conv_w + (size_t)o1 * CIN + k0 + 8));

        __half2 h0 = __floats2half2_rn(w0a.x * s00 * d0, w0a.y * s01 * d0);
        __half2 h1 = __floats2half2_rn(w1a.x * s00 * d1, w1a.y * s01 * d1);
        __half2 h2 = __floats2half2_rn(w0b.x * s08 * d0, w0b.y * s09 * d0);
        __half2 h3 = __floats2half2_rn(w1b.x * s08 * d1, w1b.y * s09 * d1);

        uint4 u;
        u.x = *(uint32_t*)&h0; u.y = *(uint32_t*)&h1;
        u.z = *(uint32_t*)&h2; u.w = *(uint32_t*)&h3;
        *(uint4*)(cb + fgrp * 128 + lane * 4) = u;
    }
}

// ---------------------------------------------------------------------------
// Kernel A3: x -> half2 k-pair layout. g_xh[b][kp][p] = half2(x[2kp][p], x[2kp+1][p])
// ---------------------------------------------------------------------------
__global__ __launch_bounds__(256) void xcvt_kernel(const float* __restrict__ x)
{
    unsigned t = blockIdx.x * 256u + threadIdx.x;   // 4,194,304 total
    unsigned p4 = t & 1023u;
    unsigned kp = (t >> 10) & 255u;
    unsigned b  = t >> 18;

    const float4* s0 = (const float4*)(x + ((size_t)b * CIN + 2 * kp) * HW) + p4;
    const float4* s1 = (const float4*)(x + ((size_t)b * CIN + 2 * kp + 1) * HW) + p4;
    float4 a = __ldg(s0);
    float4 c = __ldg(s1);

    __half2 h0 = __floats2half2_rn(a.x, c.x);
    __half2 h1 = __floats2half2_rn(a.y, c.y);
    __half2 h2 = __floats2half2_rn(a.z, c.z);
    __half2 h3 = __floats2half2_rn(a.w, c.w);
    uint4 u;
    u.x = *(uint32_t*)&h0; u.y = *(uint32_t*)&h1;
    u.z = *(uint32_t*)&h2; u.w = *(uint32_t*)&h3;
    ((uint4*)(g_xh + ((size_t)b * 256 + kp) * HW))[p4] = u;
}

// ---------------------------------------------------------------------------
// Kernel B: batched GEMM, mma.sync.m16n8k16.f16 (fp32 accum).
// CTA 128x128, chunks of k=32 (2 mma k-steps), 4-stage cp.async pipeline.
// A: fragment-ordered (LDS.128). B: [16 kp][136 half2] stride (conflict-free).
// ---------------------------------------------------------------------------
#define BSTRH 136
#define A_U32 2048                    // per stage
#define B_U32 (16 * BSTRH)            // 2176
#define STAGE_U32 (A_U32 + B_U32)     // 4224
#define NSTAGE 4
#define SM_GEMM_BYTES (NSTAGE * STAGE_U32 * 4)   // 67584

__device__ __forceinline__ uint32_t smem_u32(const void* p) {
    uint32_t a;
    asm("{ .reg .u64 t; cvta.to.shared.u64 t, %1; cvt.u32.u64 %0, t; }" : "=r"(a) : "l"(p));
    return a;
}

__global__ __launch_bounds__(256, 2) void gemm_mma(void)
{
    extern __shared__ uint32_t smu[];

    int tid = threadIdx.x;
    int wid = tid >> 5, lane = tid & 31;
    int gid = lane >> 2, tg = lane & 3;
    int b = blockIdx.z, oTile = blockIdx.y * 128, pTile = blockIdx.x * 128;
    int g = wid >> 2, wn = (wid & 3) * 32;

    const uint32_t* aglob = g_wh + ((size_t)((b * 4 + blockIdx.y) * 16)) * 2048;
    const uint32_t* xh    = g_xh + (size_t)b * 256 * HW + pTile;

    uint32_t sm_u = smem_u32(smu);
    // B cp.async coords: row = tid>>4 (kp 0..15), col = (tid&15)*8 half2
    int bkr = tid >> 4, bpc = (tid & 15) * 8;

    auto issue = [&](int ch) {
        int buf = ch & (NSTAGE - 1);
        uint32_t stage = sm_u + buf * STAGE_U32 * 4;
        const uint32_t* as_ = aglob + ch * 2048 + tid * 8;
        uint32_t ad = stage + tid * 32;
        asm volatile("cp.async.cg.shared.global [%0], [%1], 16;" :: "r"(ad),      "l"(as_)     : "memory");
        asm volatile("cp.async.cg.shared.global [%0], [%1], 16;" :: "r"(ad + 16), "l"(as_ + 4) : "memory");
        const uint32_t* bs_ = xh + (size_t)(ch * 16 + bkr) * HW + bpc;
        uint32_t bd = stage + (A_U32 + bkr * BSTRH + bpc) * 4;
        asm volatile("cp.async.cg.shared.global [%0], [%1], 16;" :: "r"(bd),      "l"(bs_)     : "memory");
        asm volatile("cp.async.cg.shared.global [%0], [%1], 16;" :: "r"(bd + 16), "l"(bs_ + 4) : "memory");
        asm volatile("cp.async.commit_group;" ::: "memory");
    };

    float c[4][4][4];
#pragma unroll
    for (int mt = 0; mt < 4; mt++)
#pragma unroll
        for (int nt = 0; nt < 4; nt++)
#pragma unroll
            for (int q = 0; q < 4; q++) c[mt][nt][q] = 0.f;

    issue(0); issue(1); issue(2);

    const int NCH = CIN / 32;   // 16
    for (int ch = 0; ch < NCH; ch++) {
        if (ch + 3 < NCH) {
            issue(ch + 3);
            asm volatile("cp.async.wait_group 3;" ::: "memory");
        } else if (ch + 2 < NCH) {
            asm volatile("cp.async.wait_group 2;" ::: "memory");
        } else if (ch + 1 < NCH) {
            asm volatile("cp.async.wait_group 1;" ::: "memory");
        } else {
            asm volatile("cp.async.wait_group 0;" ::: "memory");
        }
        __syncthreads();

        int buf = ch & (NSTAGE - 1);
        const uint32_t* Ab = smu + buf * STAGE_U32 + g * 1024;
        const uint32_t* Bb = smu + buf * STAGE_U32 + A_U32;

#pragma unroll
        for (int s = 0; s < 2; s++) {
            uint32_t af[4][4], bf[4][2];
#pragma unroll
            for (int mt = 0; mt < 4; mt++) {
                uint4 av = *(const uint4*)(Ab + (s * 4 + mt) * 128 + lane * 4);
                af[mt][0] = av.x; af[mt][1] = av.y; af[mt][2] = av.z; af[mt][3] = av.w;
            }
#pragma unroll
            for (int nt = 0; nt < 4; nt++) {
                int nb = wn + nt * 8 + gid;
                bf[nt][0] = Bb[(s * 8 + tg) * BSTRH + nb];
                bf[nt][1] = Bb[(s * 8 + tg + 4) * BSTRH + nb];
            }
#pragma unroll
            for (int mt = 0; mt < 4; mt++)
#pragma unroll
                for (int nt = 0; nt < 4; nt++) {
                    asm volatile(
                        "mma.sync.aligned.m16n8k16.row.col.f32.f16.f16.f32 "
                        "{%0,%1,%2,%3}, {%4,%5,%6,%7}, {%8,%9}, {%0,%1,%2,%3};"
                        : "+f"(c[mt][nt][0]), "+f"(c[mt][nt][1]),
                          "+f"(c[mt][nt][2]), "+f"(c[mt][nt][3])
                        : "r"(af[mt][0]), "r"(af[mt][1]), "r"(af[mt][2]), "r"(af[mt][3]),
                          "r"(bf[nt][0]), "r"(bf[nt][1]));
                }
        }
        __syncthreads();
    }

    float* yb = g_y + (size_t)b * COUT * HW;
#pragma unroll
    for (int mt = 0; mt < 4; mt++) {
        int r0 = oTile + g * 64 + mt * 16 + gid;
        int r1 = r0 + 8;
#pragma unroll
        for (int nt = 0; nt < 4; nt++) {
            int col = pTile + wn + nt * 8 + tg * 2;
            *(float2*)(yb + (size_t)r0 * HW + col) = make_float2(c[mt][nt][0], c[mt][nt][1]);
            *(float2*)(yb + (size_t)r1 * HW + col) = make_float2(c[mt][nt][2], c[mt][nt][3]);
        }
    }
}

// ---------------------------------------------------------------------------
// Kernel C: bilinear x2 upsample, smem-tiled. One block per (b,c) image.
// Stage 64x64 input in smem (stride 68), each lane emits aligned float2.
// Edge behavior = index clamp (matches jax.image.resize half-pixel).
// ---------------------------------------------------------------------------
__global__ __launch_bounds__(256) void upsample_kernel(float* __restrict__ out)
{
    __shared__ float ssm[64 * 68];
    unsigned c = blockIdx.x & 511u;
    unsigned b = blockIdx.x >> 9;
    int tid = threadIdx.x;
    int wid = tid >> 5, lane = tid & 31;

    const float4* src = (const float4*)(g_y + ((size_t)b * COUT + c) * HW);
#pragma unroll
    for (int j = 0; j < 4; j++) {
        int idx = tid + j * 256;            // float4 index 0..1023
        int row = idx >> 4, col4 = idx & 15;
        *(float4*)(ssm + row * 68 + col4 * 4) = __ldg(src + idx);
    }
    __syncthreads();

    float* outp = out + ((size_t)b * COUT + c) * OH * OW;
#pragma unroll
    for (int i = 0; i < 16; i++) {
        int oy = i * 8 + wid;
        float fy  = oy * 0.5f - 0.25f;
        float y0f = floorf(fy);
        float wy  = fy - y0f;
        int iy0 = max(0, (int)y0f);
        int iy1 = min(63, (int)y0f + 1);
        const float* r0 = ssm + iy0 * 68;
        const float* r1 = ssm + iy1 * 68;
        float* orow = outp + (size_t)oy * OW;
#pragma unroll
        for (int seg = 0; seg < 2; seg++) {
            int xc = lane + seg * 32;
            int xm = max(0, xc - 1);
            int xp = min(63, xc + 1);
            float vm = r0[xm] + wy * (r1[xm] - r0[xm]);
            float vc = r0[xc] + wy * (r1[xc] - r0[xc]);
            float vp = r0[xp] + wy * (r1[xp] - r0[xp]);
            *(float2*)(orow + 2 * xc) =
                make_float2(0.25f * vm + 0.75f * vc, 0.75f * vc + 0.25f * vp);
        }
    }
}

// ---------------------------------------------------------------------------
extern "C" void kernel_launch(void* const* d_in, const int* in_sizes, int n_in,
                              void* d_out, int out_size)
{
    const float* x      = (const float*)d_in[0];
    const float* style  = (const float*)d_in[1];
    const float* conv_w = (const float*)d_in[2];
    const float* mod_w  = (const float*)d_in[3];
    const float* mod_b  = (const float*)d_in[4];
    float* out = (float*)d_out;

    cudaFuncSetAttribute(gemm_mma, cudaFuncAttributeMaxDynamicSharedMemorySize, SM_GEMM_BYTES);

    dim3 mgrid(8, 16);
    mod_demod_kernel<<<mgrid, 256>>>(style, conv_w, mod_w, mod_b);

    dim3 fgrid(16, 4, 16);
    wfrag_kernel<<<fgrid, 256>>>(conv_w);

    xcvt_kernel<<<16384, 256>>>(x);

    dim3 ggrid(HW / 128, COUT / 128, B_);   // (32, 4, 16)
    gemm_mma<<<ggrid, 256, SM_GEMM_BYTES>>>();

    upsample_kernel<<<B_ * COUT, 256>>>(out);
}